// round 1
// baseline (speedup 1.0000x reference)
#include <cuda_runtime.h>
#include <cuda_bf16.h>
#include <math.h>

// ---------------------------------------------------------------------------
// RiemannianGNN: 2-layer Poincare GNN.
//   per layer: t = (logmap(x) if layer>0 else x)*mask
//              msg = (t @ W)*mask
//              c   = (sum_k w[n,k]*msg[adj[n,k]])*mask
//              x   = relu(expmap(c)*mask)*mask
// Fusion: logmap of layer 1 is fused into agg kernel of layer 0.
// ---------------------------------------------------------------------------

#define NMAX 50000
#define DD 128
#define KK 32

// scratch (no cudaMalloc allowed)
__device__ float g_msg[NMAX * DD];
__device__ float g_x[NMAX * DD];

// ---------------- GEMM: out[n,d] = (sum_k x[n,k]*W[k,d]) * mask[n] ---------
// optionally applies mask to the input rows as well (layer 0: x = node_repr*mask)
#define GR 64     // rows per block
#define GT 256    // threads per block

__global__ __launch_bounds__(GT) void gemm_kernel(
    const float* __restrict__ x, const float* __restrict__ W,
    const float* __restrict__ mask, float* __restrict__ out,
    int N, int applyInMask)
{
    extern __shared__ float sm[];
    float* Ws = sm;              // 128*128
    float* xs = sm + DD * DD;    // GR*128

    const int n0 = blockIdx.x * GR;

    // load W (16384 floats) via float4
    for (int i = threadIdx.x; i < DD * DD / 4; i += GT)
        ((float4*)Ws)[i] = ((const float4*)W)[i];

    // load x rows (GR*128 floats) via float4, apply input mask if requested
    for (int i = threadIdx.x; i < GR * DD / 4; i += GT) {
        int r = i >> 5;          // i / 32
        int c4 = i & 31;
        int n = n0 + r;
        float4 v = make_float4(0.f, 0.f, 0.f, 0.f);
        if (n < N) {
            v = ((const float4*)x)[n * 32 + c4];
            if (applyInMask) {
                float m = mask[n];
                v.x *= m; v.y *= m; v.z *= m; v.w *= m;
            }
        }
        ((float4*)xs)[i] = v;
    }
    __syncthreads();

    const int dg = threadIdx.x & 31;   // column group: cols dg*4 .. dg*4+3
    const int rg = threadIdx.x >> 5;   // row group: rows rg*8 .. rg*8+7

    float4 acc[8];
    #pragma unroll
    for (int i = 0; i < 8; i++) acc[i] = make_float4(0.f, 0.f, 0.f, 0.f);

    #pragma unroll 4
    for (int k = 0; k < DD; k++) {
        float4 wv = ((float4*)Ws)[k * 32 + dg];
        #pragma unroll
        for (int i = 0; i < 8; i++) {
            float xb = xs[(rg * 8 + i) * DD + k];
            acc[i].x = fmaf(xb, wv.x, acc[i].x);
            acc[i].y = fmaf(xb, wv.y, acc[i].y);
            acc[i].z = fmaf(xb, wv.z, acc[i].z);
            acc[i].w = fmaf(xb, wv.w, acc[i].w);
        }
    }

    #pragma unroll
    for (int i = 0; i < 8; i++) {
        int n = n0 + rg * 8 + i;
        if (n < N) {
            float m = mask[n];
            float4 v = acc[i];
            v.x *= m; v.y *= m; v.z *= m; v.w *= m;
            ((float4*)out)[n * 32 + dg] = v;
        }
    }
}

// ---------------- Aggregation + expmap + relu (+ fused logmap) -------------
// one warp per node; lane l holds cols 4l..4l+3
__global__ __launch_bounds__(256) void agg_kernel(
    const float* __restrict__ msg, const int* __restrict__ adj,
    const float* __restrict__ wgt, const float* __restrict__ mask,
    float* __restrict__ out, int N, int fuseLogmap)
{
    const int warp = (blockIdx.x * blockDim.x + threadIdx.x) >> 5;
    const int lane = threadIdx.x & 31;
    if (warp >= N) return;

    const int   myIdx = adj[warp * KK + lane];
    const float myW   = wgt[warp * KK + lane];

    float4 acc = make_float4(0.f, 0.f, 0.f, 0.f);
    #pragma unroll
    for (int j = 0; j < KK; j++) {
        int   nb = __shfl_sync(0xffffffffu, myIdx, j);
        float wj = __shfl_sync(0xffffffffu, myW,   j);
        float4 v = __ldg(((const float4*)(msg + (size_t)nb * DD)) + lane);
        acc.x = fmaf(wj, v.x, acc.x);
        acc.y = fmaf(wj, v.y, acc.y);
        acc.z = fmaf(wj, v.z, acc.z);
        acc.w = fmaf(wj, v.w, acc.w);
    }

    const float m = mask[warp];
    // combined = (...) * mask
    acc.x *= m; acc.y *= m; acc.z *= m; acc.w *= m;

    // expmap_zero: tanh(clip(||v||, eps, 15)) * v / max(||v||, eps)
    float ss = acc.x * acc.x + acc.y * acc.y + acc.z * acc.z + acc.w * acc.w;
    #pragma unroll
    for (int o = 16; o > 0; o >>= 1) ss += __shfl_xor_sync(0xffffffffu, ss, o);
    float n1 = sqrtf(ss);
    float nc1 = fminf(fmaxf(n1, 1e-5f), 15.0f);
    float s1 = tanhf(nc1) / fmaxf(n1, 1e-5f);
    s1 *= m;                                // expmap(...) * mask

    float4 e;
    e.x = acc.x * s1; e.y = acc.y * s1; e.z = acc.z * s1; e.w = acc.w * s1;
    // relu * mask
    e.x = fmaxf(e.x, 0.f) * m; e.y = fmaxf(e.y, 0.f) * m;
    e.z = fmaxf(e.z, 0.f) * m; e.w = fmaxf(e.w, 0.f) * m;

    if (fuseLogmap) {
        // next layer's logmap: atanh(clip(||y||, eps, 1-1e-5)) * y / max(||y||, eps), * mask
        float ss2 = e.x * e.x + e.y * e.y + e.z * e.z + e.w * e.w;
        #pragma unroll
        for (int o = 16; o > 0; o >>= 1) ss2 += __shfl_xor_sync(0xffffffffu, ss2, o);
        float n2 = sqrtf(ss2);
        float nc2 = fminf(fmaxf(n2, 1e-5f), 1.0f - 1e-5f);
        float s2 = atanhf(nc2) / fmaxf(n2, 1e-5f);
        s2 *= m;
        e.x *= s2; e.y *= s2; e.z *= s2; e.w *= s2;
    }

    ((float4*)out)[warp * 32 + lane] = e;
}

// ---------------------------------------------------------------------------

extern "C" void kernel_launch(void* const* d_in, const int* in_sizes, int n_in,
                              void* d_out, int out_size)
{
    const float* node_repr = (const float*)d_in[0];   // [N,128]
    const int*   adj_mat   = (const int*)  d_in[1];   // [N,32]
    const float* weight    = (const float*)d_in[2];   // [N,32]
    const float* mask      = (const float*)d_in[3];   // [N,1]
    const float* msg_w     = (const float*)d_in[4];   // [2,128,128]
    float*       out       = (float*)d_out;

    const int N = in_sizes[0] / DD;

    float* msg; float* xbuf;
    cudaGetSymbolAddress((void**)&msg,  g_msg);
    cudaGetSymbolAddress((void**)&xbuf, g_x);

    const int smemBytes = (DD * DD + GR * DD) * sizeof(float);  // 96 KB
    cudaFuncSetAttribute(gemm_kernel, cudaFuncAttributeMaxDynamicSharedMemorySize, smemBytes);

    const int gemmBlocks = (N + GR - 1) / GR;
    const int aggBlocks  = (N * 32 + 255) / 256;

    const float* W0 = msg_w;
    const float* W1 = msg_w + DD * DD;

    // layer 0
    gemm_kernel<<<gemmBlocks, GT, smemBytes>>>(node_repr, W0, mask, msg, N, 1);
    agg_kernel <<<aggBlocks, 256>>>(msg, adj_mat, weight, mask, xbuf, N, 1);
    // layer 1 (logmap already fused into xbuf)
    gemm_kernel<<<gemmBlocks, GT, smemBytes>>>(xbuf, W1, mask, msg, N, 0);
    agg_kernel <<<aggBlocks, 256>>>(msg, adj_mat, weight, mask, out, N, 0);
}